// round 1
// baseline (speedup 1.0000x reference)
#include <cuda_runtime.h>
#include <cuda_bf16.h>
#include <math.h>

// Problem constants
#define BB   2048   // batch
#define KK   2048   // I == H == 2048 (per-phase K)
#define HH   2048
#define FH   8192   // 4*H

// GEMM tile config
#define BM 128
#define BN 128
#define BK 16
#define TM 8
#define TN 8
#define NTHREADS 256

// 64 MB scratch for gate pre-activations [B, 4H]
__device__ float g_gates[(size_t)BB * FH];

// gates = x @ W_ih^T + h @ W_hh^T + b_ih + b_hh
// A (x/h): [2048, 2048] row-major.  W: [8192, 2048] row-major (we need W^T,
// i.e. gates[m,n] = sum_k A[m,k] * W[n,k]  -> "NT" layout, both K-contiguous).
__global__ __launch_bounds__(NTHREADS, 2)
void lstm_gemm_kernel(const float* __restrict__ x,
                      const float* __restrict__ h,
                      const float* __restrict__ Wih,
                      const float* __restrict__ Whh,
                      const float* __restrict__ bih,
                      const float* __restrict__ bhh,
                      float* __restrict__ gates)
{
    __shared__ float As[BK][BM];
    __shared__ float Bs[BK][BN];

    const int tid = threadIdx.x;
    const int m0  = blockIdx.y * BM;
    const int n0  = blockIdx.x * BN;

    // compute-thread microtile coords (16x16 threads of 8x8)
    const int tm = (tid / 16) * TM;
    const int tn = (tid % 16) * TN;

    // load coords: each thread loads 2 float4 from A and 2 from W per BK chunk
    const int lr   = tid >> 2;          // 0..63
    const int lc4  = (tid & 3) * 4;     // 0,4,8,12

    float acc[TM][TN];
    #pragma unroll
    for (int i = 0; i < TM; ++i)
        #pragma unroll
        for (int j = 0; j < TN; ++j)
            acc[i][j] = 0.0f;

    const float* Aptrs[2] = {x, h};
    const float* Wptrs[2] = {Wih, Whh};

    for (int phase = 0; phase < 2; ++phase) {
        const float* __restrict__ A = Aptrs[phase];
        const float* __restrict__ W = Wptrs[phase];

        for (int k0 = 0; k0 < KK; k0 += BK) {
            // Global loads (issue before sync to overlap with prior compute)
            float4 a0 = *(const float4*)&A[(size_t)(m0 + lr     ) * KK + k0 + lc4];
            float4 a1 = *(const float4*)&A[(size_t)(m0 + lr + 64) * KK + k0 + lc4];
            float4 b0 = *(const float4*)&W[(size_t)(n0 + lr     ) * KK + k0 + lc4];
            float4 b1 = *(const float4*)&W[(size_t)(n0 + lr + 64) * KK + k0 + lc4];

            __syncthreads();   // previous iteration's compute done reading smem

            // Store transposed: As[k][m], Bs[k][n]
            As[lc4 + 0][lr     ] = a0.x;
            As[lc4 + 1][lr     ] = a0.y;
            As[lc4 + 2][lr     ] = a0.z;
            As[lc4 + 3][lr     ] = a0.w;
            As[lc4 + 0][lr + 64] = a1.x;
            As[lc4 + 1][lr + 64] = a1.y;
            As[lc4 + 2][lr + 64] = a1.z;
            As[lc4 + 3][lr + 64] = a1.w;

            Bs[lc4 + 0][lr     ] = b0.x;
            Bs[lc4 + 1][lr     ] = b0.y;
            Bs[lc4 + 2][lr     ] = b0.z;
            Bs[lc4 + 3][lr     ] = b0.w;
            Bs[lc4 + 0][lr + 64] = b1.x;
            Bs[lc4 + 1][lr + 64] = b1.y;
            Bs[lc4 + 2][lr + 64] = b1.z;
            Bs[lc4 + 3][lr + 64] = b1.w;

            __syncthreads();

            #pragma unroll
            for (int kk = 0; kk < BK; ++kk) {
                float a[TM], b[TN];
                #pragma unroll
                for (int i = 0; i < TM; ++i) a[i] = As[kk][tm + i];
                #pragma unroll
                for (int j = 0; j < TN; ++j) b[j] = Bs[kk][tn + j];
                #pragma unroll
                for (int i = 0; i < TM; ++i)
                    #pragma unroll
                    for (int j = 0; j < TN; ++j)
                        acc[i][j] = fmaf(a[i], b[j], acc[i][j]);
            }
        }
    }

    // Epilogue: add biases and store gate pre-activations
    float bias[TN];
    #pragma unroll
    for (int j = 0; j < TN; ++j) {
        int n = n0 + tn + j;
        bias[j] = bih[n] + bhh[n];
    }
    #pragma unroll
    for (int i = 0; i < TM; ++i) {
        const int m = m0 + tm + i;
        float4* dst = (float4*)&gates[(size_t)m * FH + n0 + tn];
        float4 v0, v1;
        v0.x = acc[i][0] + bias[0];
        v0.y = acc[i][1] + bias[1];
        v0.z = acc[i][2] + bias[2];
        v0.w = acc[i][3] + bias[3];
        v1.x = acc[i][4] + bias[4];
        v1.y = acc[i][5] + bias[5];
        v1.z = acc[i][6] + bias[6];
        v1.w = acc[i][7] + bias[7];
        dst[0] = v0;
        dst[1] = v1;
    }
}

__device__ __forceinline__ float sigmoidf_(float v) {
    return 1.0f / (1.0f + expf(-v));
}

// Pointwise LSTM epilogue: reads gates [B,4H] + C_prev, writes 6 x [B,H]
// outputs concatenated in reference return order:
// (new_h, new_C, forget_gate, input_gate, candidate_gate, output_gate)
__global__ void lstm_pointwise_kernel(const float* __restrict__ gates,
                                      const float* __restrict__ Cprev,
                                      float* __restrict__ out)
{
    const int idx = blockIdx.x * blockDim.x + threadIdx.x;
    const int total = BB * HH;
    if (idx >= total) return;

    const int m = idx >> 11;        // /2048
    const int n = idx & (HH - 1);   // %2048

    const float* __restrict__ grow = gates + (size_t)m * FH;
    const float gi = grow[n];
    const float gf = grow[HH + n];
    const float gg = grow[2 * HH + n];
    const float go = grow[3 * HH + n];

    const float ig = sigmoidf_(gi);
    const float fg = sigmoidf_(gf);
    const float cg = tanhf(gg);
    const float og = sigmoidf_(go);

    const float C  = Cprev[idx];
    const float nC = fg * C + ig * cg;
    const float nh = og * tanhf(nC);

    const size_t S = (size_t)total;
    out[          idx] = nh;
    out[    S +   idx] = nC;
    out[2 * S +   idx] = fg;
    out[3 * S +   idx] = ig;
    out[4 * S +   idx] = cg;
    out[5 * S +   idx] = og;
}

extern "C" void kernel_launch(void* const* d_in, const int* in_sizes, int n_in,
                              void* d_out, int out_size)
{
    const float* x     = (const float*)d_in[0];  // [2048, 2048]
    const float* hprev = (const float*)d_in[1];  // [2048, 2048]
    const float* Cprev = (const float*)d_in[2];  // [2048, 2048]
    const float* Wih   = (const float*)d_in[3];  // [8192, 2048]
    const float* bih   = (const float*)d_in[4];  // [8192]
    const float* Whh   = (const float*)d_in[5];  // [8192, 2048]
    const float* bhh   = (const float*)d_in[6];  // [8192]
    float* out = (float*)d_out;

    float* gates;
    cudaGetSymbolAddress((void**)&gates, g_gates);

    dim3 gemm_grid(FH / BN, BB / BM);   // (64, 16)
    lstm_gemm_kernel<<<gemm_grid, NTHREADS>>>(x, hprev, Wih, Whh, bih, bhh, gates);

    const int total = BB * HH;
    lstm_pointwise_kernel<<<(total + 255) / 256, 256>>>(gates, Cprev, out);
}

// round 4
// speedup vs baseline: 2.9766x; 2.9766x over previous
#include <cuda_runtime.h>
#include <cuda_bf16.h>
#include <cstdint>
#include <math.h>

// ---------------- problem constants ----------------
#define BB 2048
#define KK 2048
#define HH 2048
#define FH 8192

// ---------------- GEMM config ----------------
#define BM 128
#define BN 128
#define BK 32              // bf16 K elems per chunk
#define NTH 256            // 8 warps: 2 (M) x 4 (N)
#define NCHUNK 128         // 2 phases * (2048/32)
#define ROWB 128           // smem row bytes: hi[32]|lo[32] bf16 = 64B+64B
#define OFF_B 16384        // B tile offset within stage (A = 128*128B = 16KB)
#define STAGE_BYTES 32768
#define SMEM_TOTAL (2*STAGE_BYTES)

// ---------------- scratch (device globals; no alloc) ----------------
__device__ __align__(16) __nv_bfloat16 g_ah[2][(size_t)BB*KK];  // x_hi, h_hi
__device__ __align__(16) __nv_bfloat16 g_al[2][(size_t)BB*KK];  // x_lo, h_lo
__device__ __align__(16) __nv_bfloat16 g_wh[2][(size_t)FH*KK];  // Wih_hi, Whh_hi
__device__ __align__(16) __nv_bfloat16 g_wl[2][(size_t)FH*KK];  // Wih_lo, Whh_lo
__device__ __align__(16) float g_gates[(size_t)BB*FH];

// ---------------- PTX helpers (plain sm_100-safe) ----------------
__device__ __forceinline__ uint32_t smem_u32(const void* p) {
    return (uint32_t)__cvta_generic_to_shared(p);
}
__device__ __forceinline__ void cp16(uint32_t s, const void* g) {
    asm volatile("cp.async.cg.shared.global [%0], [%1], 16;"
                 :: "r"(s), "l"(__cvta_generic_to_global(g)) : "memory");
}
__device__ __forceinline__ void cp_commit() {
    asm volatile("cp.async.commit_group;" ::: "memory");
}
template <int N>
__device__ __forceinline__ void cp_wait() {
    asm volatile("cp.async.wait_group %0;" :: "n"(N) : "memory");
}
__device__ __forceinline__ void ldsm4(uint32_t* r, uint32_t a) {
    asm volatile("ldmatrix.sync.aligned.m8n8.x4.shared.b16 {%0,%1,%2,%3}, [%4];"
                 : "=r"(r[0]), "=r"(r[1]), "=r"(r[2]), "=r"(r[3]) : "r"(a));
}
__device__ __forceinline__ void mma16816(float* c, const uint32_t* a, const uint32_t* b) {
    asm volatile(
        "mma.sync.aligned.m16n8k16.row.col.f32.bf16.bf16.f32 "
        "{%0,%1,%2,%3}, {%4,%5,%6,%7}, {%8,%9}, {%0,%1,%2,%3};"
        : "+f"(c[0]), "+f"(c[1]), "+f"(c[2]), "+f"(c[3])
        : "r"(a[0]), "r"(a[1]), "r"(a[2]), "r"(a[3]), "r"(b[0]), "r"(b[1]));
}
__device__ __forceinline__ uint32_t swz(uint32_t x) {   // SW128: bits[6:4] ^= bits[9:7]
    return x ^ ((x >> 3) & 0x70);
}

// ---------------- split fp32 -> bf16 hi/lo ----------------
__global__ void split_kernel(const float4* __restrict__ src,
                             __nv_bfloat162* __restrict__ hi,
                             __nv_bfloat162* __restrict__ lo, int n4)
{
    int i = blockIdx.x * blockDim.x + threadIdx.x;
    if (i >= n4) return;
    float4 v = src[i];
    __nv_bfloat16 h0 = __float2bfloat16(v.x);
    __nv_bfloat16 h1 = __float2bfloat16(v.y);
    __nv_bfloat16 h2 = __float2bfloat16(v.z);
    __nv_bfloat16 h3 = __float2bfloat16(v.w);
    __nv_bfloat16 l0 = __float2bfloat16(v.x - __bfloat162float(h0));
    __nv_bfloat16 l1 = __float2bfloat16(v.y - __bfloat162float(h1));
    __nv_bfloat16 l2 = __float2bfloat16(v.z - __bfloat162float(h2));
    __nv_bfloat16 l3 = __float2bfloat16(v.w - __bfloat162float(h3));
    hi[2 * i]     = __nv_bfloat162(h0, h1);
    hi[2 * i + 1] = __nv_bfloat162(h2, h3);
    lo[2 * i]     = __nv_bfloat162(l0, l1);
    lo[2 * i + 1] = __nv_bfloat162(l2, l3);
}

// ---------------- tile loader: one K-chunk (A 16KB + B 16KB) into a stage ----------------
// SMEM row layout (128B): [ hi k0..k31 (64B) | lo k0..k31 (64B) ], SW128-swizzled.
__device__ __forceinline__ void load_chunk(int c, uint32_t stage, int m0, int n0, int tid)
{
    const int ph = c >> 6;
    const int k0 = (c & 63) * BK;
    const __nv_bfloat16* __restrict__ Ah = g_ah[ph];
    const __nv_bfloat16* __restrict__ Al = g_al[ph];
    const __nv_bfloat16* __restrict__ Wh = g_wh[ph];
    const __nv_bfloat16* __restrict__ Wl = g_wl[ph];

    #pragma unroll
    for (int j = 0; j < 4; ++j) {          // A: 1024 x 16B
        int idx = tid + j * NTH;
        int r = idx >> 3, cb = idx & 7;
        uint32_t so = swz((uint32_t)(r * ROWB + cb * 16));
        const __nv_bfloat16* src = (cb < 4)
            ? Ah + (size_t)(m0 + r) * KK + k0 + (cb & 3) * 8
            : Al + (size_t)(m0 + r) * KK + k0 + (cb & 3) * 8;
        cp16(stage + so, src);
    }
    #pragma unroll
    for (int j = 0; j < 4; ++j) {          // B: 1024 x 16B
        int idx = tid + j * NTH;
        int r = idx >> 3, cb = idx & 7;
        uint32_t so = swz((uint32_t)(r * ROWB + cb * 16));
        const __nv_bfloat16* src = (cb < 4)
            ? Wh + (size_t)(n0 + r) * KK + k0 + (cb & 3) * 8
            : Wl + (size_t)(n0 + r) * KK + k0 + (cb & 3) * 8;
        cp16(stage + OFF_B + so, src);
    }
}

// ---------------- split-bf16 mma.sync GEMM: gates[m,n] = sum_k A[m,k]*W[n,k] ----------------
__global__ __launch_bounds__(NTH, 2)
void lstm_gemm_mma(float* __restrict__ gates)
{
    extern __shared__ __align__(1024) char smem[];
    const uint32_t sb = smem_u32(smem);
    const int tid = threadIdx.x;
    const int wid = tid >> 5;
    const int l   = tid & 31;
    const int m0  = blockIdx.y * BM;
    const int n0  = blockIdx.x * BN;
    const int wm  = wid & 1;      // 0..1 -> 64-row slab
    const int wn  = wid >> 1;     // 0..3 -> 32-col slab

    float acc[4][4][4];
    #pragma unroll
    for (int mt = 0; mt < 4; ++mt)
        #pragma unroll
        for (int nt = 0; nt < 4; ++nt)
            #pragma unroll
            for (int q = 0; q < 4; ++q) acc[mt][nt][q] = 0.0f;

    // Tile-relative SWIZZLED ldmatrix offsets.  Per-ks (+32B) is applied by
    // XOR at use (pre-swizzle col bit5 is always 0 and 32's bits don't feed
    // the swizzle mask, so swz(u+32) == swz(u)^32).  Stage/base offsets are
    // plain adds (>= bit 14, swizzled offsets stay < 16384/32768).
    uint32_t swzA[4][2];   // [mt][hi|lo]
    #pragma unroll
    for (int mt = 0; mt < 4; ++mt) {
        int r = wm * 64 + mt * 16 + (l & 15);
        #pragma unroll
        for (int hl = 0; hl < 2; ++hl)
            swzA[mt][hl] = swz((uint32_t)(r * ROWB + hl * 64 + (l >> 4) * 16));
    }
    uint32_t swzB[2][2];   // [np][hi|lo]
    #pragma unroll
    for (int np = 0; np < 2; ++np) {
        int r = wn * 32 + np * 16 + ((l >> 4) << 3) + (l & 7);
        #pragma unroll
        for (int hl = 0; hl < 2; ++hl)
            swzB[np][hl] = OFF_B +
                swz((uint32_t)(r * ROWB + hl * 64 + ((l >> 3) & 1) * 16));
    }

    // prologue
    load_chunk(0, sb, m0, n0, tid);
    cp_commit();
    load_chunk(1, sb + STAGE_BYTES, m0, n0, tid);
    cp_commit();

    for (int c = 0; c < NCHUNK; ++c) {
        const uint32_t base = sb + (uint32_t)(c & 1) * STAGE_BYTES;

        cp_wait<1>();
        __syncthreads();

        #pragma unroll
        for (int ks = 0; ks < 2; ++ks) {
            const uint32_t kx = (uint32_t)ks << 5;   // XOR-applied k-step
            uint32_t bh[2][4], bl[2][4];
            #pragma unroll
            for (int np = 0; np < 2; ++np) {
                ldsm4(bh[np], base + (swzB[np][0] ^ kx));
                ldsm4(bl[np], base + (swzB[np][1] ^ kx));
            }
            #pragma unroll
            for (int mt = 0; mt < 4; ++mt) {
                uint32_t ah[4], al[4];
                ldsm4(ah, base + (swzA[mt][0] ^ kx));
                ldsm4(al, base + (swzA[mt][1] ^ kx));
                #pragma unroll
                for (int nt = 0; nt < 4; ++nt) {
                    const uint32_t* bhp = &bh[nt >> 1][(nt & 1) * 2];
                    const uint32_t* blp = &bl[nt >> 1][(nt & 1) * 2];
                    mma16816(acc[mt][nt], ah, bhp);
                    mma16816(acc[mt][nt], ah, blp);
                    mma16816(acc[mt][nt], al, bhp);
                }
            }
        }

        __syncthreads();
        if (c + 2 < NCHUNK)
            load_chunk(c + 2, base, m0, n0, tid);
        cp_commit();           // keep group accounting fixed
    }

    // epilogue: fragment layout -> gates
    const int rbase = m0 + wm * 64 + (l >> 2);
    const int cbase = n0 + wn * 32 + 2 * (l & 3);
    #pragma unroll
    for (int mt = 0; mt < 4; ++mt) {
        #pragma unroll
        for (int nt = 0; nt < 4; ++nt) {
            const int r = rbase + mt * 16;
            const int cc = cbase + nt * 8;
            float2 v0 = make_float2(acc[mt][nt][0], acc[mt][nt][1]);
            float2 v1 = make_float2(acc[mt][nt][2], acc[mt][nt][3]);
            *(float2*)&gates[(size_t)r * FH + cc]       = v0;
            *(float2*)&gates[(size_t)(r + 8) * FH + cc] = v1;
        }
    }
}

// ---------------- pointwise LSTM epilogue (bias folded in) ----------------
__device__ __forceinline__ float sigmoidf_(float v) { return 1.0f / (1.0f + expf(-v)); }

__global__ void lstm_pointwise(const float* __restrict__ gates,
                               const float* __restrict__ Cprev,
                               const float* __restrict__ bih,
                               const float* __restrict__ bhh,
                               float* __restrict__ out)
{
    const int i4 = blockIdx.x * blockDim.x + threadIdx.x;
    const int total4 = BB * HH / 4;
    if (i4 >= total4) return;

    const int m = i4 / (HH / 4);
    const int n = (i4 % (HH / 4)) * 4;

    const float* __restrict__ grow = gates + (size_t)m * FH;
    float4 gi = *(const float4*)(grow + n);
    float4 gf = *(const float4*)(grow + HH + n);
    float4 gg = *(const float4*)(grow + 2 * HH + n);
    float4 go = *(const float4*)(grow + 3 * HH + n);

    float4 b0a = *(const float4*)(bih + n);
    float4 b0b = *(const float4*)(bhh + n);
    float4 b1a = *(const float4*)(bih + HH + n);
    float4 b1b = *(const float4*)(bhh + HH + n);
    float4 b2a = *(const float4*)(bih + 2 * HH + n);
    float4 b2b = *(const float4*)(bhh + 2 * HH + n);
    float4 b3a = *(const float4*)(bih + 3 * HH + n);
    float4 b3b = *(const float4*)(bhh + 3 * HH + n);

    float4 C = *(const float4*)(Cprev + (size_t)m * HH + n);

    float4 vh, vC, vf, vi, vg, vo;
    float* pgi = &gi.x; float* pgf = &gf.x; float* pgg = &gg.x; float* pgo = &go.x;
    float* pb0a = &b0a.x; float* pb0b = &b0b.x; float* pb1a = &b1a.x; float* pb1b = &b1b.x;
    float* pb2a = &b2a.x; float* pb2b = &b2b.x; float* pb3a = &b3a.x; float* pb3b = &b3b.x;
    float* pC = &C.x;
    float* ph = &vh.x; float* pc = &vC.x; float* pf = &vf.x; float* pi = &vi.x;
    float* pg = &vg.x; float* po = &vo.x;

    #pragma unroll
    for (int q = 0; q < 4; ++q) {
        float ig = sigmoidf_(pgi[q] + pb0a[q] + pb0b[q]);
        float fg = sigmoidf_(pgf[q] + pb1a[q] + pb1b[q]);
        float cg = tanhf(pgg[q] + pb2a[q] + pb2b[q]);
        float og = sigmoidf_(pgo[q] + pb3a[q] + pb3b[q]);
        float nC = fg * pC[q] + ig * cg;
        pf[q] = fg; pi[q] = ig; pg[q] = cg; po[q] = og;
        pc[q] = nC;
        ph[q] = og * tanhf(nC);
    }

    const size_t S = (size_t)BB * HH;
    const size_t idx = (size_t)m * HH + n;
    *(float4*)(out + idx)         = vh;
    *(float4*)(out + S + idx)     = vC;
    *(float4*)(out + 2 * S + idx) = vf;
    *(float4*)(out + 3 * S + idx) = vi;
    *(float4*)(out + 4 * S + idx) = vg;
    *(float4*)(out + 5 * S + idx) = vo;
}

// ---------------- launch ----------------
extern "C" void kernel_launch(void* const* d_in, const int* in_sizes, int n_in,
                              void* d_out, int out_size)
{
    const float* x     = (const float*)d_in[0];
    const float* hprev = (const float*)d_in[1];
    const float* Cprev = (const float*)d_in[2];
    const float* Wih   = (const float*)d_in[3];
    const float* bih   = (const float*)d_in[4];
    const float* Whh   = (const float*)d_in[5];
    const float* bhh   = (const float*)d_in[6];
    float* out = (float*)d_out;

    __nv_bfloat16 *ah, *al, *wh, *wl;
    float* gates;
    cudaGetSymbolAddress((void**)&ah, g_ah);
    cudaGetSymbolAddress((void**)&al, g_al);
    cudaGetSymbolAddress((void**)&wh, g_wh);
    cudaGetSymbolAddress((void**)&wl, g_wl);
    cudaGetSymbolAddress((void**)&gates, g_gates);

    static bool attr_set = false;
    if (!attr_set) {
        cudaFuncSetAttribute(lstm_gemm_mma,
                             cudaFuncAttributeMaxDynamicSharedMemorySize, SMEM_TOTAL);
        attr_set = true;
    }

    const int nA4 = BB * KK / 4;
    const int nW4 = FH * KK / 4;
    const size_t A = (size_t)BB * KK;
    const size_t W = (size_t)FH * KK;

    split_kernel<<<(nA4 + 255) / 256, 256>>>((const float4*)x,
        (__nv_bfloat162*)ah, (__nv_bfloat162*)al, nA4);
    split_kernel<<<(nA4 + 255) / 256, 256>>>((const float4*)hprev,
        (__nv_bfloat162*)(ah + A), (__nv_bfloat162*)(al + A), nA4);
    split_kernel<<<(nW4 + 255) / 256, 256>>>((const float4*)Wih,
        (__nv_bfloat162*)wh, (__nv_bfloat162*)wl, nW4);
    split_kernel<<<(nW4 + 255) / 256, 256>>>((const float4*)Whh,
        (__nv_bfloat162*)(wh + W), (__nv_bfloat162*)(wl + W), nW4);

    dim3 grid(FH / BN, BB / BM);   // (64, 16)
    lstm_gemm_mma<<<grid, NTH, SMEM_TOTAL>>>(gates);

    const int total4 = BB * HH / 4;
    lstm_pointwise<<<(total4 + 255) / 256, 256>>>(gates, Cprev, bih, bhh, out);
}